// round 15
// baseline (speedup 1.0000x reference)
#include <cuda_runtime.h>
#include <cstdint>

// Model_25855703122577: inputs [8192,784,1] f32, W_ih[30,1], W_hh[30,30],
// b_mod[30], W_lin[10,30], b_lin[10] -> out [8192,10] f32
#define RB    8192
#define RT    784
#define RH    30
#define RC    10
#define GRP   8        // lanes per batch element (4 parallel groups per warp)
#define RPT   4        // rows per lane (8*4 = 32; rows 30,31 zero pads)
#define KP    15       // k-pairs (exact)
#define TPB   32       // one warp per block
#define SLOTS 8        // batches per warp: 4 parallel groups x 2 serial sets
#define HSTR  36       // floats per slot (144B: 16B-aligned slot bases)

typedef unsigned long long u64;

__device__ __forceinline__ u64 fmul2(u64 a, u64 b) {
    u64 d; asm("mul.rn.f32x2 %0, %1, %2;" : "=l"(d) : "l"(a), "l"(b)); return d;
}
__device__ __forceinline__ u64 ffma2(u64 a, u64 b, u64 c) {
    u64 d; asm("fma.rn.f32x2 %0, %1, %2, %3;" : "=l"(d) : "l"(a), "l"(b), "l"(c)); return d;
}
__device__ __forceinline__ u64 pack2(float lo, float hi) {
    u64 d; asm("mov.b64 %0, {%1, %2};" : "=l"(d) : "f"(lo), "f"(hi)); return d;
}
__device__ __forceinline__ void unpack2(u64 v, float& lo, float& hi) {
    asm("mov.b64 {%0, %1}, %2;" : "=f"(lo), "=f"(hi) : "l"(v));
}

// One t-step for TWO batch sets (A,B): this lane's 4 rows of each set's
// batch. 8 independent FFMA2 chains + 2 independent load streams give one
// warp ~2x the ready-instruction supply -> the in-order issue stream can
// keep the fma pipe fed even at 1.75 warps/SMSP.
// h streamed as 2x8 LDS.128 through 2-deep rings (live set 16 regs).
// x*W_ih folded into accumulator init: acc = wihx*{x,x} = {x*wih, 0}.
__device__ __forceinline__ void rnn_step2(
    float xa, float xb,
    const u64 (&w)[RPT][KP],
    const u64 (&wihx)[RPT],
    const float (&bm)[RPT],
    const float* srcA, const float* srcB,
    float* dstA, float* dstB)
{
    const ulonglong2* hpA = reinterpret_cast<const ulonglong2*>(srcA);
    const ulonglong2* hpB = reinterpret_cast<const ulonglong2*>(srcB);

    ulonglong2 ra0 = hpA[0];
    ulonglong2 rb0 = hpB[0];
    ulonglong2 ra1 = hpA[1];
    ulonglong2 rb1 = hpB[1];

    const u64 xxA = pack2(xa, xa);
    const u64 xxB = pack2(xb, xb);
    u64 aA[RPT], aB[RPT];
#pragma unroll
    for (int r = 0; r < RPT; r++) {
        aA[r] = fmul2(wihx[r], xxA);   // {x*wih, 0}
        aB[r] = fmul2(wihx[r], xxB);
    }

    // chunk 0 (pairs 0,1)
#pragma unroll
    for (int r = 0; r < RPT; r++) {
        aA[r] = ffma2(w[r][0], ra0.x, aA[r]);
        aB[r] = ffma2(w[r][0], rb0.x, aB[r]);
    }
#pragma unroll
    for (int r = 0; r < RPT; r++) {
        aA[r] = ffma2(w[r][1], ra0.y, aA[r]);
        aB[r] = ffma2(w[r][1], rb0.y, aB[r]);
    }
    ra0 = hpA[2]; rb0 = hpB[2];
    // chunk 1 (pairs 2,3)
#pragma unroll
    for (int r = 0; r < RPT; r++) {
        aA[r] = ffma2(w[r][2], ra1.x, aA[r]);
        aB[r] = ffma2(w[r][2], rb1.x, aB[r]);
    }
#pragma unroll
    for (int r = 0; r < RPT; r++) {
        aA[r] = ffma2(w[r][3], ra1.y, aA[r]);
        aB[r] = ffma2(w[r][3], rb1.y, aB[r]);
    }
    ra1 = hpA[3]; rb1 = hpB[3];
    // chunk 2 (pairs 4,5)
#pragma unroll
    for (int r = 0; r < RPT; r++) {
        aA[r] = ffma2(w[r][4], ra0.x, aA[r]);
        aB[r] = ffma2(w[r][4], rb0.x, aB[r]);
    }
#pragma unroll
    for (int r = 0; r < RPT; r++) {
        aA[r] = ffma2(w[r][5], ra0.y, aA[r]);
        aB[r] = ffma2(w[r][5], rb0.y, aB[r]);
    }
    ra0 = hpA[4]; rb0 = hpB[4];
    // chunk 3 (pairs 6,7)
#pragma unroll
    for (int r = 0; r < RPT; r++) {
        aA[r] = ffma2(w[r][6], ra1.x, aA[r]);
        aB[r] = ffma2(w[r][6], rb1.x, aB[r]);
    }
#pragma unroll
    for (int r = 0; r < RPT; r++) {
        aA[r] = ffma2(w[r][7], ra1.y, aA[r]);
        aB[r] = ffma2(w[r][7], rb1.y, aB[r]);
    }
    ra1 = hpA[5]; rb1 = hpB[5];
    // chunk 4 (pairs 8,9)
#pragma unroll
    for (int r = 0; r < RPT; r++) {
        aA[r] = ffma2(w[r][8], ra0.x, aA[r]);
        aB[r] = ffma2(w[r][8], rb0.x, aB[r]);
    }
#pragma unroll
    for (int r = 0; r < RPT; r++) {
        aA[r] = ffma2(w[r][9], ra0.y, aA[r]);
        aB[r] = ffma2(w[r][9], rb0.y, aB[r]);
    }
    ra0 = hpA[6]; rb0 = hpB[6];
    // chunk 5 (pairs 10,11)
#pragma unroll
    for (int r = 0; r < RPT; r++) {
        aA[r] = ffma2(w[r][10], ra1.x, aA[r]);
        aB[r] = ffma2(w[r][10], rb1.x, aB[r]);
    }
#pragma unroll
    for (int r = 0; r < RPT; r++) {
        aA[r] = ffma2(w[r][11], ra1.y, aA[r]);
        aB[r] = ffma2(w[r][11], rb1.y, aB[r]);
    }
    ra1 = hpA[7]; rb1 = hpB[7];
    // chunk 6 (pairs 12,13)
#pragma unroll
    for (int r = 0; r < RPT; r++) {
        aA[r] = ffma2(w[r][12], ra0.x, aA[r]);
        aB[r] = ffma2(w[r][12], rb0.x, aB[r]);
    }
#pragma unroll
    for (int r = 0; r < RPT; r++) {
        aA[r] = ffma2(w[r][13], ra0.y, aA[r]);
        aB[r] = ffma2(w[r][13], rb0.y, aB[r]);
    }
    // chunk 7: pair 14 only (pair 15 = zero pad: skipped)
#pragma unroll
    for (int r = 0; r < RPT; r++) {
        aA[r] = ffma2(w[r][14], ra1.x, aA[r]);
        aB[r] = ffma2(w[r][14], rb1.x, aB[r]);
    }

    float hvA[RPT], hvB[RPT];
#pragma unroll
    for (int r = 0; r < RPT; r++) {
        float lo, hi;
        unpack2(aA[r], lo, hi);
        float zA = lo + hi;              // includes x*wih from the init
        unpack2(aB[r], lo, hi);
        float zB = lo + hi;
        // modReLU: copysign(relu(|z|+b), z); z==0 -> +0 (pad rows stay 0)
        float mA = fmaxf(fabsf(zA) + bm[r], 0.0f);
        float mB = fmaxf(fabsf(zB) + bm[r], 0.0f);
        hvA[r] = copysignf(mA, zA);
        hvB[r] = copysignf(mB, zB);
    }
    *reinterpret_cast<float4*>(dstA) = make_float4(hvA[0], hvA[1], hvA[2], hvA[3]);
    *reinterpret_cast<float4*>(dstB) = make_float4(hvB[0], hvB[1], hvB[2], hvB[3]);
    // Warp-synchronous exchange (validated R12/R13): converged warp,
    // STS->LDS program order on hbuf; compiler-only fence per step.
    asm volatile("" ::: "memory");
}

extern "C" __global__ void __launch_bounds__(TPB)
rnn_modrelu_kernel(const float* __restrict__ inputs,  // [B, T]
                   const float* __restrict__ W_ih,    // [H]
                   const float* __restrict__ W_hh,    // [H, H]
                   const float* __restrict__ b_mod,   // [H]
                   const float* __restrict__ W_lin,   // [C, H]
                   const float* __restrict__ b_lin,   // [C]
                   float* __restrict__ out)           // [B, C]
{
    __shared__ __align__(16) float hbuf[2][SLOTS][HSTR];

    const int lane = threadIdx.x;       // 0..31
    const int sub  = lane & (GRP - 1);  // 0..7 row-slice
    const int g    = lane >> 3;         // 0..3 parallel group
    const int sA   = g;                 // set-A slot
    const int sB   = g + 4;             // set-B slot
    const int bA   = blockIdx.x * SLOTS + sA;
    const int bB   = blockIdx.x * SLOTS + sB;

    // ---- register weight slice: 4 rows x 15 pairs = 120 regs ----
    u64 w[RPT][KP];
    u64 wihx[RPT];
    float bm[RPT];
#pragma unroll
    for (int r = 0; r < RPT; r++) {
        const int row = sub * RPT + r;
        if (row < RH) {
            const u64* wr = reinterpret_cast<const u64*>(W_hh + row * RH);
#pragma unroll
            for (int p = 0; p < KP; p++) w[r][p] = wr[p];
            wihx[r] = pack2(W_ih[row], 0.0f);
            bm[r]   = b_mod[row];
        } else {            // rows 30,31: all-zero -> stay exactly 0 forever
#pragma unroll
            for (int p = 0; p < KP; p++) w[r][p] = 0ULL;
            wihx[r] = 0ULL;
            bm[r]   = 0.0f;
        }
    }

    // h0 = 0 (each lane zeroes its float4 in both its slots)
    *reinterpret_cast<float4*>(&hbuf[0][sA][sub * 4]) = make_float4(0, 0, 0, 0);
    *reinterpret_cast<float4*>(&hbuf[0][sB][sub * 4]) = make_float4(0, 0, 0, 0);
    __syncwarp();

    const float* xrA = inputs + (size_t)bA * RT;
    const float* xrB = inputs + (size_t)bB * RT;

#pragma unroll 1
    for (int t0 = 0; t0 < RT; t0 += 2) {
        const float2 xa = *reinterpret_cast<const float2*>(xrA + t0);
        const float2 xb = *reinterpret_cast<const float2*>(xrB + t0);
        rnn_step2(xa.x, xb.x, w, wihx, bm,
                  &hbuf[0][sA][0], &hbuf[0][sB][0],
                  &hbuf[1][sA][sub * 4], &hbuf[1][sB][sub * 4]);
        rnn_step2(xa.y, xb.y, w, wihx, bm,
                  &hbuf[1][sA][0], &hbuf[1][sB][0],
                  &hbuf[0][sA][sub * 4], &hbuf[0][sB][sub * 4]);
    }
    // T=784 even -> final h in buffer 0
    __syncwarp();   // one-time, before cross-lane classifier reads

    // ---- fused classifier: out[b][c] = h . W_lin[c] + b_lin[c] ----
#pragma unroll 1
    for (int pass = 0; pass < 2; pass++) {
        const int slot = (pass == 0) ? sA : sB;
        const int b    = (pass == 0) ? bA : bB;
        const float* hf = &hbuf[0][slot][0];
#pragma unroll 1
        for (int c = sub; c < RC; c += GRP) {
            float acc = b_lin[c];
            const float* wl = W_lin + c * RH;
#pragma unroll
            for (int k = 0; k < RH; k++) acc = fmaf(hf[k], wl[k], acc);
            out[(size_t)b * RC + c] = acc;
        }
    }
}

extern "C" void kernel_launch(void* const* d_in, const int* in_sizes, int n_in,
                              void* d_out, int out_size) {
    const float* inputs = (const float*)d_in[0];
    const float* W_ih   = (const float*)d_in[1];
    const float* W_hh   = (const float*)d_in[2];
    const float* b_mod  = (const float*)d_in[3];
    const float* W_lin  = (const float*)d_in[4];
    const float* b_lin  = (const float*)d_in[5];
    float* out = (float*)d_out;

    dim3 grid(RB / SLOTS);   // 1024 one-warp blocks; ~7/SM needed, cap >= 10
    dim3 block(TPB);
    rnn_modrelu_kernel<<<grid, block>>>(inputs, W_ih, W_hh, b_mod,
                                        W_lin, b_lin, out);
}

// round 17
// speedup vs baseline: 1.5016x; 1.5016x over previous
#include <cuda_runtime.h>
#include <cuda_bf16.h>
#include <cstdint>

// Model_25855703122577: inputs [8192,784,1] f32, W_ih[30,1], W_hh[30,30],
// b_mod[30], W_lin[10,30], b_lin[10] -> out [8192,10] f32
//
// Tensor-core recurrence via mma.sync.m16n8k16 (bf16, f32 accum) — the
// arch-portable HMMA path (tcgen05 needs compute_103a PTX; harness emits
// compute_103). One warp owns 16 batches; h lives ONLY in registers as an
// exact 2-term bf16 split (hhi+hlo). D-fragment layout == A-fragment layout,
// so D -> modReLU -> split -> next A is in-register: no smem, no syncs.
//   z = (hhi+hlo)(Whi+Wlo)^T  (4 split products, fp32 accumulation)
//   x*W_ih folded via K-cols 30,31 of A = (xhi,xlo), B rows 30,31 = wih hi/lo.
#define RB 8192
#define RT 784
#define RH 30
#define RC 10

typedef uint32_t u32;

// pack two floats to bf16x2: lower half = first arg
__device__ __forceinline__ u32 bf16x2_of(float lo, float hi) {
    u32 r; asm("cvt.rn.bf16x2.f32 %0, %1, %2;" : "=r"(r) : "f"(hi), "f"(lo));
    return r;
}
__device__ __forceinline__ float bf_lo(u32 p) { return __uint_as_float(p << 16); }
__device__ __forceinline__ float bf_hi(u32 p) { return __uint_as_float(p & 0xffff0000u); }

__device__ __forceinline__ void mma16816(float (&d)[4], const u32 (&a)[4],
                                         const u32 (&b)[2]) {
    asm volatile(
        "mma.sync.aligned.m16n8k16.row.col.f32.bf16.bf16.f32 "
        "{%0,%1,%2,%3}, {%4,%5,%6,%7}, {%8,%9}, {%0,%1,%2,%3};"
        : "+f"(d[0]), "+f"(d[1]), "+f"(d[2]), "+f"(d[3])
        : "r"(a[0]), "r"(a[1]), "r"(a[2]), "r"(a[3]), "r"(b[0]), "r"(b[1]));
}

__device__ __forceinline__ float modrelu(float z, float b) {
    // copysign(relu(|z|+b), z); z==0 -> +0 (validated vs reference since R7)
    return copysignf(fmaxf(fabsf(z) + b, 0.0f), z);
}

// modReLU two D values (one row, two adjacent cols) -> (hi, lo) bf16x2 pair
__device__ __forceinline__ void conv2(float z0, float z1, float b0, float b1,
                                      u32& hi, u32& lo) {
    const float h0 = modrelu(z0, b0);
    const float h1 = modrelu(z1, b1);
    hi = bf16x2_of(h0, h1);
    lo = bf16x2_of(h0 - bf_lo(hi), h1 - bf_hi(hi));
}

// exact 2-term bf16 split of x packed as (xhi, xlo)
__device__ __forceinline__ u32 xsplit(float x) {
    const u32 t = bf16x2_of(x, 0.0f);
    const float xh = bf_lo(t);
    return bf16x2_of(xh, x - xh);
}

extern "C" __global__ void __launch_bounds__(32)
rnn_mma_kernel(const float* __restrict__ inputs,  // [B, T]
               const float* __restrict__ W_ih,    // [H]
               const float* __restrict__ W_hh,    // [H, H]
               const float* __restrict__ b_mod,   // [H]
               const float* __restrict__ W_lin,   // [C, H]
               const float* __restrict__ b_lin,   // [C]
               float* __restrict__ out)           // [B, C]
{
    __shared__ float hsm[16][32];

    const int lane = threadIdx.x;
    const int g    = lane >> 2;       // fragment group row 0..7
    const int tig  = lane & 3;        // thread-in-group 0..3
    const int w    = blockIdx.x;      // warp id = batch tile
    const int rowA = w * 16 + g;      // batch rows g and g+8
    const int rowB = rowA + 8;
    const bool isx = (tig == 3);      // owns K-cols 30,31 in ktile1

    // ---- B fragments: B[k][n] = W_hh[n][k] (k<30), = wih hi/lo (k=30,31) ----
    // col-major k16n8 fragment: b0 = (k=2tig,2tig+1, n=g), b1 = (+8)
    u32 bhi[4][2][2], blo[4][2][2];
#pragma unroll
    for (int nt = 0; nt < 4; nt++) {
        const int n = g + 8 * nt;
#pragma unroll
        for (int kt = 0; kt < 2; kt++) {
#pragma unroll
            for (int half = 0; half < 2; half++) {
                const int k0 = kt * 16 + 2 * tig + 8 * half;   // even
                float v0 = 0.0f, v1 = 0.0f;
                if (n < RH) {
                    v0 = (k0     < RH) ? W_hh[n * RH + k0]     : W_ih[n];
                    v1 = (k0 + 1 < RH) ? W_hh[n * RH + k0 + 1] : W_ih[n];
                }
                const u32 hi = bf16x2_of(v0, v1);
                bhi[nt][kt][half] = hi;
                blo[nt][kt][half] = bf16x2_of(v0 - bf_lo(hi), v1 - bf_hi(hi));
            }
        }
    }

    // ---- b_mod for this lane's 8 columns (cols = 8*nt + 2*tig + j) ----
    float bmv[8];
#pragma unroll
    for (int nt = 0; nt < 4; nt++) {
#pragma unroll
        for (int j = 0; j < 2; j++) {
            const int col = 8 * nt + 2 * tig + j;
            bmv[2 * nt + j] = (col < RH) ? __ldg(b_mod + col) : 0.0f;
        }
    }

    const float* xrA = inputs + (size_t)rowA * RT;
    const float* xrB = inputs + (size_t)rowB * RT;

    // ---- initial A: h0 = 0; ktile1 cols 30,31 = x_0 split (tig==3 lanes) ----
    u32 ahi0[4] = {0, 0, 0, 0}, alo0[4] = {0, 0, 0, 0};
    u32 ahi1[4] = {0, 0, 0, 0}, alo1[4] = {0, 0, 0, 0};
    {
        const u32 xpA = xsplit(__ldg(xrA));
        const u32 xpB = xsplit(__ldg(xrB));
        ahi1[2] = isx ? xpA : 0u;       // row g,   cols 30,31
        ahi1[3] = isx ? xpB : 0u;       // row g+8, cols 30,31
    }

#pragma unroll 1
    for (int t = 0; t < RT; t++) {
        // prefetch next x (clamped; value unused at t = RT-1)
        const int tn = (t + 1 < RT) ? t + 1 : t;
        const float xAn = __ldg(xrA + tn);
        const float xBn = __ldg(xrB + tn);

        float d0[4] = {0, 0, 0, 0}, d1[4] = {0, 0, 0, 0};
        float d2[4] = {0, 0, 0, 0}, d3[4] = {0, 0, 0, 0};

        // 32 HMMA: 4 independent accumulator chains (one per n-tile)
        mma16816(d0, ahi0, bhi[0][0]); mma16816(d1, ahi0, bhi[1][0]);
        mma16816(d2, ahi0, bhi[2][0]); mma16816(d3, ahi0, bhi[3][0]);
        mma16816(d0, ahi1, bhi[0][1]); mma16816(d1, ahi1, bhi[1][1]);
        mma16816(d2, ahi1, bhi[2][1]); mma16816(d3, ahi1, bhi[3][1]);
        mma16816(d0, alo0, bhi[0][0]); mma16816(d1, alo0, bhi[1][0]);
        mma16816(d2, alo0, bhi[2][0]); mma16816(d3, alo0, bhi[3][0]);
        mma16816(d0, alo1, bhi[0][1]); mma16816(d1, alo1, bhi[1][1]);
        mma16816(d2, alo1, bhi[2][1]); mma16816(d3, alo1, bhi[3][1]);
        mma16816(d0, ahi0, blo[0][0]); mma16816(d1, ahi0, blo[1][0]);
        mma16816(d2, ahi0, blo[2][0]); mma16816(d3, ahi0, blo[3][0]);
        mma16816(d0, ahi1, blo[0][1]); mma16816(d1, ahi1, blo[1][1]);
        mma16816(d2, ahi1, blo[2][1]); mma16816(d3, ahi1, blo[3][1]);
        mma16816(d0, alo0, blo[0][0]); mma16816(d1, alo0, blo[1][0]);
        mma16816(d2, alo0, blo[2][0]); mma16816(d3, alo0, blo[3][0]);
        mma16816(d0, alo1, blo[0][1]); mma16816(d1, alo1, blo[1][1]);
        mma16816(d2, alo1, blo[2][1]); mma16816(d3, alo1, blo[3][1]);

        // ---- epilogue: D -> modReLU -> exact bf16 split -> next A (regs) ----
        // D(c0,c1): row g; D(c2,c3): row g+8 — same layout as A reg pairs.
        conv2(d0[0], d0[1], bmv[0], bmv[1], ahi0[0], alo0[0]);  // cols 2tig
        conv2(d0[2], d0[3], bmv[0], bmv[1], ahi0[1], alo0[1]);
        conv2(d1[0], d1[1], bmv[2], bmv[3], ahi0[2], alo0[2]);  // cols 8+2tig
        conv2(d1[2], d1[3], bmv[2], bmv[3], ahi0[3], alo0[3]);
        conv2(d2[0], d2[1], bmv[4], bmv[5], ahi1[0], alo1[0]);  // cols 16+2tig
        conv2(d2[2], d2[3], bmv[4], bmv[5], ahi1[1], alo1[1]);
        u32 h30, l30, h31, l31;
        conv2(d3[0], d3[1], bmv[6], bmv[7], h30, l30);          // cols 24+2tig
        conv2(d3[2], d3[3], bmv[6], bmv[7], h31, l31);
        // tig==3 lanes: replace cols 30,31 with next x split
        ahi1[2] = isx ? xsplit(xAn) : h30;
        ahi1[3] = isx ? xsplit(xBn) : h31;
        alo1[2] = isx ? 0u : l30;
        alo1[3] = isx ? 0u : l31;
    }

    // ---- spill final h (= hi+lo, exact by construction) to smem ----
    const int c0 = 2 * tig;
    hsm[g][c0]          = bf_lo(ahi0[0]) + bf_lo(alo0[0]);
    hsm[g][c0 + 1]      = bf_hi(ahi0[0]) + bf_hi(alo0[0]);
    hsm[g + 8][c0]      = bf_lo(ahi0[1]) + bf_lo(alo0[1]);
    hsm[g + 8][c0 + 1]  = bf_hi(ahi0[1]) + bf_hi(alo0[1]);
    hsm[g][c0 + 8]      = bf_lo(ahi0[2]) + bf_lo(alo0[2]);
    hsm[g][c0 + 9]      = bf_hi(ahi0[2]) + bf_hi(alo0[2]);
    hsm[g + 8][c0 + 8]  = bf_lo(ahi0[3]) + bf_lo(alo0[3]);
    hsm[g + 8][c0 + 9]  = bf_hi(ahi0[3]) + bf_hi(alo0[3]);
    hsm[g][c0 + 16]     = bf_lo(ahi1[0]) + bf_lo(alo1[0]);
    hsm[g][c0 + 17]     = bf_hi(ahi1[0]) + bf_hi(alo1[0]);
    hsm[g + 8][c0 + 16] = bf_lo(ahi1[1]) + bf_lo(alo1[1]);
    hsm[g + 8][c0 + 17] = bf_hi(ahi1[1]) + bf_hi(alo1[1]);
    hsm[g][c0 + 24]     = bf_lo(ahi1[2]) + bf_lo(alo1[2]);   // cols 30,31 (tig==3)
    hsm[g][c0 + 25]     = bf_hi(ahi1[2]) + bf_hi(alo1[2]);   // hold x: never read
    hsm[g + 8][c0 + 24] = bf_lo(ahi1[3]) + bf_lo(alo1[3]);
    hsm[g + 8][c0 + 25] = bf_hi(ahi1[3]) + bf_hi(alo1[3]);
    __syncwarp();

    // ---- classifier: out[b][c] = h . W_lin[c] + b_lin[c] ----
    const int r    = lane & 15;
    const int half = lane >> 4;
#pragma unroll
    for (int ci = 0; ci < 5; ci++) {
        const int c = half * 5 + ci;
        float acc = __ldg(b_lin + c);
        const float* wl = W_lin + c * RH;
#pragma unroll
        for (int k = 0; k < RH; k++) acc = fmaf(hsm[r][k], __ldg(wl + k), acc);
        out[(size_t)(w * 16 + r) * RC + c] = acc;
    }
}

extern "C" void kernel_launch(void* const* d_in, const int* in_sizes, int n_in,
                              void* d_out, int out_size) {
    const float* inputs = (const float*)d_in[0];
    const float* W_ih   = (const float*)d_in[1];
    const float* W_hh   = (const float*)d_in[2];
    const float* b_mod  = (const float*)d_in[3];
    const float* W_lin  = (const float*)d_in[4];
    const float* b_lin  = (const float*)d_in[5];
    float* out = (float*)d_out;

    dim3 grid(RB / 16);   // 512 one-warp blocks, 16 batches each
    dim3 block(32);
    rnn_mma_kernel<<<grid, block>>>(inputs, W_ih, W_hh, b_mod,
                                    W_lin, b_lin, out);
}